// round 16
// baseline (speedup 1.0000x reference)
#include <cuda_runtime.h>

#define DATA_NUM 1024
#define CLS_NUM  32000
#define R        2               // rows per CTA
#define NBG      512             // level-1 (global) histogram bins
#define NB2      1024            // level-2 (smem) sub-histogram bins
#define NT       256             // threads per CTA
#define BPTG     (NBG / NT)      // 2
#define BPT2     (NB2 / NT)      // 4
#define RANGE2   140.0f          // log2-domain window below the M2 bound
#define CAP      1024            // stash capacity per row
#define LOG2E    1.4426950408889634f
#define LN2      0.6931471805599453f

// Per-row global histogram scratch (2 MB). Zeroed by each CTA for its rows.
__device__ float g_hist[DATA_NUM][NBG];

__device__ __forceinline__ float vload(const float* p) {
    return *(const volatile float*)p;
}
__device__ __forceinline__ float ex2(float x) {
    float y; asm("ex2.approx.f32 %0, %1;" : "=f"(y) : "f"(x)); return y;
}
__device__ __forceinline__ float lg2(float x) {
    float y; asm("lg2.approx.f32 %0, %1;" : "=f"(y) : "f"(x)); return y;
}

// Fused block-wide sum of 4 values (broadcast). red: 4*NT floats.
__device__ void block_sum4(float& a, float& b, float& c, float& d, float* red) {
    int tid = threadIdx.x;
    __syncthreads();
    red[tid] = a; red[NT + tid] = b; red[2 * NT + tid] = c; red[3 * NT + tid] = d;
    __syncthreads();
#pragma unroll
    for (int s = NT / 2; s > 0; s >>= 1) {
        if (tid < s) {
            red[tid]          += red[tid + s];
            red[NT + tid]     += red[NT + tid + s];
            red[2 * NT + tid] += red[2 * NT + tid + s];
            red[3 * NT + tid] += red[3 * NT + tid + s];
        }
        __syncthreads();
    }
    a = red[0]; b = red[NT]; c = red[2 * NT]; d = red[3 * NT];
    __syncthreads();
}

// Find bin where ascending cumulative mass crosses `target` in hist[NBINS].
template <int NBINS, int BPT>
__device__ void find_crossing(const float* hist, float* red, float target,
                              int* s_bin, float* s_cdf) {
    int tid = threadIdx.x;
    __syncthreads();
    if (tid == 0) { *s_bin = NBINS - 1; *s_cdf = 0.f; }   // safe default
    float h[BPT];
    float s = 0.f;
#pragma unroll
    for (int i = 0; i < BPT; i++) { h[i] = hist[tid * BPT + i]; s += h[i]; }
    red[tid] = s;
    __syncthreads();
    if (tid == 0) {
        float c = 0.f;
        for (int i = 0; i < NT; i++) { float t = red[i]; red[i] = c; c += t; }
    }
    __syncthreads();
    float c = red[tid];
#pragma unroll
    for (int i = 0; i < BPT; i++) {
        if (c < target && c + h[i] >= target) { *s_bin = tid * BPT + i; *s_cdf = c; }
        c += h[i];
    }
    __syncthreads();
}

// ---------------------------------------------------------------------------
__global__ void zero_out(float* out) { out[0] = 0.f; }

// R rows per CTA.
__global__ void __launch_bounds__(NT) akl_kernel(
    const float* h1, const float* e1,
    const float* h3, const float* e3, float* out)
{
    __shared__ float hist2[R][NB2];       // 8 KB
    __shared__ float red[4 * NT];         // 4 KB
    __shared__ float st_sf[R][CAP];       // 8 KB (sub-bin float coordinate)
    __shared__ float st_p2[R][CAP];       // 8 KB
    __shared__ float st_gap[R][CAP];      // 8 KB
    __shared__ int   s_cnt[R];
    __shared__ float s_cdf1[R], s_cdf2[R];
    __shared__ int   s_b1[R],  s_b2[R];

    const int row0 = blockIdx.x * R;
    const int tid  = threadIdx.x;

    // Per-row coefficients (log2 domain) and analytic shift bounds.
    float a1[R], b1v[R], a3[R], b3v[R], nM1[R], nM2[R], dM[R];
#pragma unroll
    for (int r = 0; r < R; r++) {
        a1[r]  = vload(h1 + 2 * (row0 + r)) * LOG2E;
        b1v[r] = vload(h1 + 2 * (row0 + r) + 1) * LOG2E;
        a3[r]  = vload(h3 + 2 * (row0 + r)) * LOG2E;
        b3v[r] = vload(h3 + 2 * (row0 + r) + 1) * LOG2E;
        // |l| <= ||h'||*max||e_j||; max 2-D N(0,1) norm over 32k draws < 6.
        float M1 = 6.0f * sqrtf(a1[r] * a1[r] + b1v[r] * b1v[r]);
        float M2 = 6.0f * sqrtf(a3[r] * a3[r] + b3v[r] * b3v[r]);
        nM1[r] = -M1; nM2[r] = -M2; dM[r] = M2 - M1;
    }
    const float invw1 = (float)NBG / RANGE2;
    const float bias1 = (float)NBG;          // bin = l2m*invw1 + NBG

    const float2* e1v = (const float2*)e1;
    const float2* e3v = (const float2*)e3;

    // Zero these rows' global histograms.
#pragma unroll
    for (int r = 0; r < R; r++)
        for (int i = tid; i < NBG; i += NT) g_hist[row0 + r][i] = 0.f;
    if (tid < R) s_cnt[tid] = 0;
    __threadfence();
    __syncthreads();

    // ---- Pass 1: Z/S sums + level-1 histograms via fire-and-forget RED.
    float Z1[R] = {0.f, 0.f}, Z2[R] = {0.f, 0.f};
    float S1[R] = {0.f, 0.f}, S2[R] = {0.f, 0.f};
    {
        int j = tid;
        for (; j + NT < CLS_NUM; j += 2 * NT) {
            float2 w1[2], w3[2];
            w1[0] = __ldg(e1v + j); w1[1] = __ldg(e1v + j + NT);
            w3[0] = __ldg(e3v + j); w3[1] = __ldg(e3v + j + NT);
#pragma unroll
            for (int u = 0; u < 2; u++) {
#pragma unroll
                for (int r = 0; r < R; r++) {
                    float l1m = fmaf(a1[r], w1[u].x, fmaf(b1v[r], w1[u].y, nM1[r]));
                    float l2m = fmaf(a3[r], w3[u].x, fmaf(b3v[r], w3[u].y, nM2[r]));
                    float u1 = ex2(l1m);
                    float u2 = ex2(l2m);
                    Z1[r] += u1; Z2[r] += u2;
                    float dl = (l2m - l1m) + dM[r];
                    S2[r] = fmaf(u2,  dl, S2[r]);
                    S1[r] = fmaf(u1, -dl, S1[r]);
                    float bf = fmaf(l2m, invw1, bias1);
                    int b = (int)fminf(fmaxf(bf, 0.f), (float)(NBG - 1));
                    atomicAdd(&g_hist[row0 + r][b], u2);   // RED (no return)
                }
            }
        }
        for (; j < CLS_NUM; j += NT) {
            float2 v1 = __ldg(e1v + j);
            float2 v3 = __ldg(e3v + j);
#pragma unroll
            for (int r = 0; r < R; r++) {
                float l1m = fmaf(a1[r], v1.x, fmaf(b1v[r], v1.y, nM1[r]));
                float l2m = fmaf(a3[r], v3.x, fmaf(b3v[r], v3.y, nM2[r]));
                float u1 = ex2(l1m);
                float u2 = ex2(l2m);
                Z1[r] += u1; Z2[r] += u2;
                float dl = (l2m - l1m) + dM[r];
                S2[r] = fmaf(u2,  dl, S2[r]);
                S1[r] = fmaf(u1, -dl, S1[r]);
                float bf = fmaf(l2m, invw1, bias1);
                int b = (int)fminf(fmaxf(bf, 0.f), (float)(NBG - 1));
                atomicAdd(&g_hist[row0 + r][b], u2);
            }
        }
    }
    block_sum4(Z1[0], Z2[0], S1[0], S2[0], red);
    block_sum4(Z1[1], Z2[1], S1[1], S2[1], red);

    // Make REDs visible, then find level-1 crossings.
    __threadfence();
    __syncthreads();
#pragma unroll
    for (int r = 0; r < R; r++)
        find_crossing<NBG, BPTG>(g_hist[row0 + r], red, 0.5f * Z2[r],
                                 &s_b1[r], &s_cdf1[r]);

    // Pass-2 per-row constants (probability units: fold lg2(Z) into exponents).
    float nM1z[R], nM2z[R], bias1z[R], bias2z[R], b1f[R], b1f1[R];
    float cdf1p[R], lgZ1[R], lgZ2[R];
    const float w1w   = RANGE2 / (float)NBG;
    const float invw2 = (float)NB2 / w1w;
#pragma unroll
    for (int r = 0; r < R; r++) {
        lgZ1[r] = lg2(Z1[r]);
        lgZ2[r] = lg2(Z2[r]);
        nM1z[r]  = nM1[r] - lgZ1[r];
        nM2z[r]  = nM2[r] - lgZ2[r];
        bias1z[r] = bias1 + lgZ2[r] * invw1;
        int b1 = s_b1[r];
        b1f[r]  = (float)b1;
        b1f1[r] = (float)(b1 + 1);
        bias2z[r] = (float)NB2 * ((float)NBG - (float)b1) + lgZ2[r] * invw2;
        cdf1p[r] = s_cdf1[r] / Z2[r];
    }

    __syncthreads();
#pragma unroll
    for (int r = 0; r < R; r++)
        for (int b = tid; b < NB2; b += NT) hist2[r][b] = 0.f;
    __syncthreads();

    // ---- Pass 2: gap sums; crossing-bin elems -> smem sub-hist + stash
    float gh[R] = {0.f, 0.f}, gt[R] = {0.f, 0.f};
    {
        int j = tid;
        for (; j + NT < CLS_NUM; j += 2 * NT) {
            float2 w1[2], w3[2];
            w1[0] = __ldg(e1v + j); w1[1] = __ldg(e1v + j + NT);
            w3[0] = __ldg(e3v + j); w3[1] = __ldg(e3v + j + NT);
#pragma unroll
            for (int u = 0; u < 2; u++) {
#pragma unroll
                for (int r = 0; r < R; r++) {
                    float l1z = fmaf(a1[r], w1[u].x, fmaf(b1v[r], w1[u].y, nM1z[r]));
                    float l2z = fmaf(a3[r], w3[u].x, fmaf(b3v[r], w3[u].y, nM2z[r]));
                    float p2 = ex2(l2z);
                    float gap = fabsf(p2 - ex2(l1z));
                    float bfc = fminf(fmaxf(fmaf(l2z, invw1, bias1z[r]), 0.f),
                                      (float)(NBG - 1));
                    if (bfc < b1f[r])        gt[r] += gap;
                    else if (bfc >= b1f1[r]) gh[r] += gap;
                    else {
                        float sf = fmaf(l2z, invw2, bias2z[r]);
                        int s = (int)fminf(fmaxf(sf, 0.f), (float)(NB2 - 1));
                        atomicAdd(&hist2[r][s], p2);
                        int idx = atomicAdd(&s_cnt[r], 1);
                        if (idx < CAP) {
                            st_sf[r][idx] = sf; st_p2[r][idx] = p2; st_gap[r][idx] = gap;
                        }
                    }
                }
            }
        }
        for (; j < CLS_NUM; j += NT) {
            float2 v1 = __ldg(e1v + j);
            float2 v3 = __ldg(e3v + j);
#pragma unroll
            for (int r = 0; r < R; r++) {
                float l1z = fmaf(a1[r], v1.x, fmaf(b1v[r], v1.y, nM1z[r]));
                float l2z = fmaf(a3[r], v3.x, fmaf(b3v[r], v3.y, nM2z[r]));
                float p2 = ex2(l2z);
                float gap = fabsf(p2 - ex2(l1z));
                float bfc = fminf(fmaxf(fmaf(l2z, invw1, bias1z[r]), 0.f),
                                  (float)(NBG - 1));
                if (bfc < b1f[r])        gt[r] += gap;
                else if (bfc >= b1f1[r]) gh[r] += gap;
                else {
                    float sf = fmaf(l2z, invw2, bias2z[r]);
                    int s = (int)fminf(fmaxf(sf, 0.f), (float)(NB2 - 1));
                    atomicAdd(&hist2[r][s], p2);
                    int idx = atomicAdd(&s_cnt[r], 1);
                    if (idx < CAP) {
                        st_sf[r][idx] = sf; st_p2[r][idx] = p2; st_gap[r][idx] = gap;
                    }
                }
            }
        }
    }

    // ---- Level-2 crossings (targets in probability units)
#pragma unroll
    for (int r = 0; r < R; r++)
        find_crossing<NB2, BPT2>(hist2[r], red, 0.5f - cdf1p[r],
                                 &s_b2[r], &s_cdf2[r]);
    __syncthreads();

#pragma unroll
    for (int r = 0; r < R; r++) {
        const int   b2    = s_b2[r];
        const float cdf2p = cdf1p[r] + s_cdf2[r];
        const int m = s_cnt[r];
        if (m <= CAP) {
            for (int i = tid; i < m; i += NT) {
                int s = (int)fminf(fmaxf(st_sf[r][i], 0.f), (float)(NB2 - 1));
                bool tail;
                if (s != b2) tail = (s < b2);
                else         tail = (cdf2p + st_p2[r][i]) < 0.5f;
                if (tail) gt[r] += st_gap[r][i]; else gh[r] += st_gap[r][i];
            }
        } else {
            // Rare degenerate row: exact rescan of crossing-bin elements
            for (int j = tid; j < CLS_NUM; j += NT) {
                float2 v3 = __ldg(e3v + j);
                float l2z = fmaf(a3[r], v3.x, fmaf(b3v[r], v3.y, nM2z[r]));
                float bfc = fminf(fmaxf(fmaf(l2z, invw1, bias1z[r]), 0.f),
                                  (float)(NBG - 1));
                if (bfc >= b1f[r] && bfc < b1f1[r]) {
                    float2 v1 = __ldg(e1v + j);
                    float l1z = fmaf(a1[r], v1.x, fmaf(b1v[r], v1.y, nM1z[r]));
                    float p2 = ex2(l2z);
                    float gap = fabsf(p2 - ex2(l1z));
                    float sf = fmaf(l2z, invw2, bias2z[r]);
                    int s = (int)fminf(fmaxf(sf, 0.f), (float)(NB2 - 1));
                    bool tail;
                    if (s != b2) tail = (s < b2);
                    else         tail = (cdf2p + p2) < 0.5f;
                    if (tail) gt[r] += gap; else gh[r] += gap;
                }
            }
        }
    }
    block_sum4(gh[0], gt[0], gh[1], gt[1], red);

    if (tid == 0) {
        float acc = 0.f;
#pragma unroll
        for (int r = 0; r < R; r++) {
            float C21 = LN2 * (dM[r] + lgZ2[r] - lgZ1[r]);
            float fkl = LN2 * S2[r] / Z2[r] - C21;
            float rkl = LN2 * S1[r] / Z1[r] + C21;
            acc += (gh[r] * fkl + gt[r] * rkl) / (gh[r] + gt[r]);
        }
        atomicAdd(out, acc * (1.0f / (float)DATA_NUM));
    }
}

// ---------------------------------------------------------------------------
extern "C" void kernel_launch(void* const* d_in, const int* in_sizes, int n_in,
                              void* d_out, int out_size) {
    const float *h1 = 0, *h3 = 0, *e1 = 0, *e3 = 0;
    for (int i = 0; i < n_in; i++) {
        int s = in_sizes[i];
        if (s == 2 * DATA_NUM || s == 2 * DATA_NUM * 4) {
            if (!h1) h1 = (const float*)d_in[i]; else if (!h3) h3 = (const float*)d_in[i];
        } else if (s == 2 * CLS_NUM || s == 2 * CLS_NUM * 4) {
            if (!e1) e1 = (const float*)d_in[i]; else if (!e3) e3 = (const float*)d_in[i];
        }
    }
    if (!h1 || !h3 || !e1 || !e3) {
        h1 = (const float*)d_in[0];
        e1 = (const float*)d_in[1];
        h3 = (const float*)d_in[2];
        e3 = (const float*)d_in[3];
    }

    float* out = (float*)d_out;
    zero_out<<<1, 1>>>(out);
    akl_kernel<<<DATA_NUM / R, NT>>>(h1, e1, h3, e3, out);
}

// round 17
// speedup vs baseline: 1.1927x; 1.1927x over previous
#include <cuda_runtime.h>

#define DATA_NUM 1024
#define CLS_NUM  32000
#define NPAIR    (CLS_NUM / 2)   // 16000 float4 element-pairs
#define NBG      512             // level-1 (global) histogram bins
#define NB2      2048            // level-2 (smem) sub-histogram bins
#define NT       256             // threads per CTA
#define BPTG     (NBG / NT)      // 2
#define BPT2     (NB2 / NT)      // 8
#define RANGE2   140.0f          // log2-domain window below the M2 bound
#define CAP      2048            // stash capacity for crossing-bin elements
#define LOG2E    1.4426950408889634f
#define LN2      0.6931471805599453f

// Per-row global histogram scratch (2 MB). Zeroed by each CTA for its row.
__device__ float g_hist[DATA_NUM][NBG];

__device__ __forceinline__ float vload(const float* p) {
    return *(const volatile float*)p;
}
__device__ __forceinline__ float ex2(float x) {
    float y; asm("ex2.approx.f32 %0, %1;" : "=f"(y) : "f"(x)); return y;
}

// Block-wide sum via shared-memory tree. red: NT floats.
__device__ float block_sum(float v, float* red) {
    int tid = threadIdx.x;
    __syncthreads();
    red[tid] = v;
    __syncthreads();
#pragma unroll
    for (int s = NT / 2; s > 0; s >>= 1) {
        if (tid < s) red[tid] += red[tid + s];
        __syncthreads();
    }
    float r = red[0];
    __syncthreads();
    return r;
}

// Find bin where ascending cumulative mass crosses `target` in hist[NBINS].
template <int NBINS, int BPT>
__device__ void find_crossing(const float* hist, float* red, float target,
                              int* s_bin, float* s_cdf) {
    int tid = threadIdx.x;
    __syncthreads();
    if (tid == 0) { *s_bin = NBINS - 1; *s_cdf = 0.f; }   // safe default
    float h[BPT];
    float s = 0.f;
#pragma unroll
    for (int i = 0; i < BPT; i++) { h[i] = hist[tid * BPT + i]; s += h[i]; }
    red[tid] = s;
    __syncthreads();
    if (tid == 0) {
        float c = 0.f;
        for (int i = 0; i < NT; i++) { float t = red[i]; red[i] = c; c += t; }
    }
    __syncthreads();
    float c = red[tid];
#pragma unroll
    for (int i = 0; i < BPT; i++) {
        if (c < target && c + h[i] >= target) { *s_bin = tid * BPT + i; *s_cdf = c; }
        c += h[i];
    }
    __syncthreads();
}

// ---------------------------------------------------------------------------
__global__ void zero_out(float* out) { out[0] = 0.f; }

// One CTA per data row. float4 loads: one load pair feeds TWO elements.
__global__ void __launch_bounds__(NT) akl_kernel(
    const float* h1, const float* e1,
    const float* h3, const float* e3, float* out)
{
    __shared__ float hist2[NB2];        // 8 KB (level-2 sub-hist)
    __shared__ float red[NT];           // 1 KB
    __shared__ float st_l2[CAP];        // 8 KB
    __shared__ float st_u2[CAP];        // 8 KB
    __shared__ float st_gap[CAP];       // 8 KB
    __shared__ int   s_cnt;
    __shared__ float s_cdf1, s_cdf2;
    __shared__ int   s_b1,   s_b2;

    const int row = blockIdx.x;
    const int tid = threadIdx.x;
    float* ghist = g_hist[row];

    // Row coefficients pre-scaled by log2(e): all logits in log2 domain.
    const float a1 = vload(h1 + 2 * row) * LOG2E, b1v = vload(h1 + 2 * row + 1) * LOG2E;
    const float a3 = vload(h3 + 2 * row) * LOG2E, b3v = vload(h3 + 2 * row + 1) * LOG2E;
    // |l| <= ||h'||*max||e_j||; max 2-D N(0,1) norm over 32k draws < 6 w.o.p.
    const float M1 = 6.0f * sqrtf(a1 * a1 + b1v * b1v);
    const float M2 = 6.0f * sqrtf(a3 * a3 + b3v * b3v);
    const float nM1 = -M1, nM2 = -M2;
    const float dM  = M2 - M1;
    const float invw1 = (float)NBG / RANGE2;
    const float bias1 = (float)NBG;          // bin = l2m*invw1 + NBG

    const float4* e1q = (const float4*)e1;   // e1q[k] = elements 2k, 2k+1
    const float4* e3q = (const float4*)e3;

    // Zero this row's global histogram.
#pragma unroll
    for (int i = 0; i < BPTG; i++) ghist[tid + i * NT] = 0.f;
    if (tid == 0) s_cnt = 0;
    __threadfence();
    __syncthreads();

    // ---- Pass 1: Z/S sums + level-1 histogram via fire-and-forget RED.
    float Z1 = 0.f, Z2 = 0.f, S1 = 0.f, S2 = 0.f;
    {
        int k = tid;
        for (; k + 3 * NT < NPAIR; k += 4 * NT) {
            float4 q1[4], q3[4];
#pragma unroll
            for (int u = 0; u < 4; u++) q1[u] = __ldg(e1q + k + u * NT);
#pragma unroll
            for (int u = 0; u < 4; u++) q3[u] = __ldg(e3q + k + u * NT);
#pragma unroll
            for (int u = 0; u < 4; u++) {
#pragma unroll
                for (int h = 0; h < 2; h++) {
                    float x1 = h ? q1[u].z : q1[u].x, y1 = h ? q1[u].w : q1[u].y;
                    float x3 = h ? q3[u].z : q3[u].x, y3 = h ? q3[u].w : q3[u].y;
                    float l1m = fmaf(a1, x1, fmaf(b1v, y1, nM1));
                    float l2m = fmaf(a3, x3, fmaf(b3v, y3, nM2));
                    float u1 = ex2(l1m);
                    float u2 = ex2(l2m);
                    Z1 += u1; Z2 += u2;
                    float dl = (l2m - l1m) + dM;
                    S2 = fmaf(u2,  dl, S2);
                    S1 = fmaf(u1, -dl, S1);
                    float bf = fmaf(l2m, invw1, bias1);
                    int b = (int)fminf(fmaxf(bf, 0.f), (float)(NBG - 1));
                    atomicAdd(&ghist[b], u2);   // RED (no return)
                }
            }
        }
        for (; k < NPAIR; k += NT) {
            float4 q1 = __ldg(e1q + k);
            float4 q3 = __ldg(e3q + k);
#pragma unroll
            for (int h = 0; h < 2; h++) {
                float x1 = h ? q1.z : q1.x, y1 = h ? q1.w : q1.y;
                float x3 = h ? q3.z : q3.x, y3 = h ? q3.w : q3.y;
                float l1m = fmaf(a1, x1, fmaf(b1v, y1, nM1));
                float l2m = fmaf(a3, x3, fmaf(b3v, y3, nM2));
                float u1 = ex2(l1m);
                float u2 = ex2(l2m);
                Z1 += u1; Z2 += u2;
                float dl = (l2m - l1m) + dM;
                S2 = fmaf(u2,  dl, S2);
                S1 = fmaf(u1, -dl, S1);
                float bf = fmaf(l2m, invw1, bias1);
                int b = (int)fminf(fmaxf(bf, 0.f), (float)(NBG - 1));
                atomicAdd(&ghist[b], u2);
            }
        }
    }
    Z1 = block_sum(Z1, red);
    Z2 = block_sum(Z2, red);
    S1 = block_sum(S1, red);
    S2 = block_sum(S2, red);
    const float halfZ2 = 0.5f * Z2;

    __threadfence();
    __syncthreads();

    // ---- Level-1 crossing bin (read back from global)
    find_crossing<NBG, BPTG>(ghist, red, halfZ2, &s_b1, &s_cdf1);
    const int   b1   = s_b1;
    const float cdf1 = s_cdf1;

    const float b1f = (float)b1, b1f1 = (float)(b1 + 1);
    const float w1w   = RANGE2 / (float)NBG;
    const float invw2 = (float)NB2 / w1w;
    const float bias2 = (float)NB2 * ((float)NBG - (float)b1);

    __syncthreads();
    for (int b = tid; b < NB2; b += NT) hist2[b] = 0.f;
    __syncthreads();

    // ---- Pass 2: gap sums; crossing-bin elems -> smem sub-hist + stash
    const float invZ1 = 1.0f / Z1, invZ2 = 1.0f / Z2;
    float gh = 0.f, gt = 0.f;
    {
        int k = tid;
        for (; k + 3 * NT < NPAIR; k += 4 * NT) {
            float4 q1[4], q3[4];
#pragma unroll
            for (int u = 0; u < 4; u++) q1[u] = __ldg(e1q + k + u * NT);
#pragma unroll
            for (int u = 0; u < 4; u++) q3[u] = __ldg(e3q + k + u * NT);
#pragma unroll
            for (int u = 0; u < 4; u++) {
#pragma unroll
                for (int h = 0; h < 2; h++) {
                    float x1 = h ? q1[u].z : q1[u].x, y1 = h ? q1[u].w : q1[u].y;
                    float x3 = h ? q3[u].z : q3[u].x, y3 = h ? q3[u].w : q3[u].y;
                    float l1m = fmaf(a1, x1, fmaf(b1v, y1, nM1));
                    float l2m = fmaf(a3, x3, fmaf(b3v, y3, nM2));
                    float u2 = ex2(l2m);
                    float gap = fabsf(u2 * invZ2 - ex2(l1m) * invZ1);
                    float bfc = fminf(fmaxf(fmaf(l2m, invw1, bias1), 0.f),
                                      (float)(NBG - 1));
                    if (bfc < b1f)        gt += gap;
                    else if (bfc >= b1f1) gh += gap;
                    else {
                        float sf = fmaf(l2m, invw2, bias2);
                        int s = (int)fminf(fmaxf(sf, 0.f), (float)(NB2 - 1));
                        atomicAdd(&hist2[s], u2);
                        int idx = atomicAdd(&s_cnt, 1);
                        if (idx < CAP) { st_l2[idx] = l2m; st_u2[idx] = u2; st_gap[idx] = gap; }
                    }
                }
            }
        }
        for (; k < NPAIR; k += NT) {
            float4 q1 = __ldg(e1q + k);
            float4 q3 = __ldg(e3q + k);
#pragma unroll
            for (int h = 0; h < 2; h++) {
                float x1 = h ? q1.z : q1.x, y1 = h ? q1.w : q1.y;
                float x3 = h ? q3.z : q3.x, y3 = h ? q3.w : q3.y;
                float l1m = fmaf(a1, x1, fmaf(b1v, y1, nM1));
                float l2m = fmaf(a3, x3, fmaf(b3v, y3, nM2));
                float u2 = ex2(l2m);
                float gap = fabsf(u2 * invZ2 - ex2(l1m) * invZ1);
                float bfc = fminf(fmaxf(fmaf(l2m, invw1, bias1), 0.f),
                                  (float)(NBG - 1));
                if (bfc < b1f)        gt += gap;
                else if (bfc >= b1f1) gh += gap;
                else {
                    float sf = fmaf(l2m, invw2, bias2);
                    int s = (int)fminf(fmaxf(sf, 0.f), (float)(NB2 - 1));
                    atomicAdd(&hist2[s], u2);
                    int idx = atomicAdd(&s_cnt, 1);
                    if (idx < CAP) { st_l2[idx] = l2m; st_u2[idx] = u2; st_gap[idx] = gap; }
                }
            }
        }
    }

    // ---- Level-2 crossing within the smem sub-histogram
    find_crossing<NB2, BPT2>(hist2, red, halfZ2 - cdf1, &s_b2, &s_cdf2);
    const int   b2   = s_b2;
    const float cdf2 = cdf1 + s_cdf2;
    __syncthreads();
    const int m = s_cnt;

    if (m <= CAP) {
        for (int i = tid; i < m; i += NT) {
            float sf = fmaf(st_l2[i], invw2, bias2);
            int s = (int)fminf(fmaxf(sf, 0.f), (float)(NB2 - 1));
            bool tail;
            if (s != b2) tail = (s < b2);
            else         tail = (cdf2 + st_u2[i]) < halfZ2;
            if (tail) gt += st_gap[i]; else gh += st_gap[i];
        }
    } else {
        // Rare degenerate row: exact rescan of crossing-bin elements
        for (int j = tid; j < CLS_NUM; j += NT) {
            float x3 = vload(e3 + 2 * j), y3 = vload(e3 + 2 * j + 1);
            float l2m = fmaf(a3, x3, fmaf(b3v, y3, nM2));
            float bfc = fminf(fmaxf(fmaf(l2m, invw1, bias1), 0.f),
                              (float)(NBG - 1));
            if (bfc >= b1f && bfc < b1f1) {
                float x1 = vload(e1 + 2 * j), y1 = vload(e1 + 2 * j + 1);
                float l1m = fmaf(a1, x1, fmaf(b1v, y1, nM1));
                float u2 = ex2(l2m);
                float gap = fabsf(u2 * invZ2 - ex2(l1m) * invZ1);
                float sf = fmaf(l2m, invw2, bias2);
                int s = (int)fminf(fmaxf(sf, 0.f), (float)(NB2 - 1));
                bool tail;
                if (s != b2) tail = (s < b2);
                else         tail = (cdf2 + u2) < halfZ2;
                if (tail) gt += gap; else gh += gap;
            }
        }
    }
    gh = block_sum(gh, red);
    gt = block_sum(gt, red);

    if (tid == 0) {
        // log2-domain sums -> nats
        float C21 = LN2 * (M2 - M1) + (__logf(Z2) - __logf(Z1));
        float fkl = LN2 * S2 / Z2 - C21;
        float rkl = LN2 * S1 / Z1 + C21;
        float denom = gh + gt;
        float akl = (gh * fkl + gt * rkl) / denom;
        atomicAdd(out, akl * (1.0f / (float)DATA_NUM));
    }
}

// ---------------------------------------------------------------------------
extern "C" void kernel_launch(void* const* d_in, const int* in_sizes, int n_in,
                              void* d_out, int out_size) {
    const float *h1 = 0, *h3 = 0, *e1 = 0, *e3 = 0;
    for (int i = 0; i < n_in; i++) {
        int s = in_sizes[i];
        if (s == 2 * DATA_NUM || s == 2 * DATA_NUM * 4) {
            if (!h1) h1 = (const float*)d_in[i]; else if (!h3) h3 = (const float*)d_in[i];
        } else if (s == 2 * CLS_NUM || s == 2 * CLS_NUM * 4) {
            if (!e1) e1 = (const float*)d_in[i]; else if (!e3) e3 = (const float*)d_in[i];
        }
    }
    if (!h1 || !h3 || !e1 || !e3) {
        h1 = (const float*)d_in[0];
        e1 = (const float*)d_in[1];
        h3 = (const float*)d_in[2];
        e3 = (const float*)d_in[3];
    }

    float* out = (float*)d_out;
    zero_out<<<1, 1>>>(out);
    akl_kernel<<<DATA_NUM, NT>>>(h1, e1, h3, e3, out);
}